// round 3
// baseline (speedup 1.0000x reference)
#include <cuda_runtime.h>
#include <math.h>

#define B_   512
#define T_   128
#define DIN  256
#define U_   512
#define NPRE 1536   // [z | r | h] precomputed input projections

// Scratch (static device arrays — allocation-free rule)
__device__ float g_pre[(size_t)T_ * B_ * NPRE];  // [t][b][1536]
__device__ float g_h  [(size_t)T_ * B_ * U_];    // [t][b][512]

typedef unsigned long long ull;

__device__ __forceinline__ ull dup2(float v) {
    ull r; asm("mov.b64 %0, {%1, %1};" : "=l"(r) : "f"(v)); return r;
}
__device__ __forceinline__ void fma2(ull& d, ull a, ull b) {
    asm("fma.rn.f32x2 %0, %1, %2, %0;" : "+l"(d) : "l"(a), "l"(b));
}
__device__ __forceinline__ float2 unpk(ull v) {
    float2 f; asm("mov.b64 {%0, %1}, %2;" : "=f"(f.x), "=f"(f.y) : "l"(v)); return f;
}
__device__ __forceinline__ float f4c(const float4& v, int j) {
    return j == 0 ? v.x : (j == 1 ? v.y : (j == 2 ? v.z : v.w));
}
__device__ __forceinline__ float sigf(float x) {
    return 1.0f / (1.0f + expf(-x));
}

// ============================================================================
// Phase 1: pre[t][b][0:1536] = x[b][t][:] @ [Wzx | Wrx | Whx]
// M=65536 (m = b*128 + t), N=1536, K=256. 128x128 tiles, BK=8, 8x8/thread, f32x2.
// ============================================================================
__global__ void __launch_bounds__(256) k_pre(
    const float* __restrict__ X,
    const float* __restrict__ Wzx, const float* __restrict__ Wrx, const float* __restrict__ Whx,
    float* __restrict__ pre)
{
    __shared__ __align__(16) float As[8][128];   // [k][m] transposed
    __shared__ __align__(16) float Bs[8][128];   // [k][n]

    const int tid = threadIdx.x;
    const int bm = blockIdx.x, bn = blockIdx.y;
    const int gate = (bn * 128) >> 9;                 // each 128-wide tile is within one gate
    const float* Wg = gate == 0 ? Wzx : (gate == 1 ? Wrx : Whx);
    const int ncol0 = bn * 128 - gate * 512;

    const int tx = tid & 15, ty = tid >> 4;
    const int m0 = ty * 8, n0 = tx * 8;

    const int arow = tid >> 1, acol = (tid & 1) * 4;
    const int brow = tid >> 5, bcol = (tid & 31) * 4;
    const float* Ap = X  + (size_t)(bm * 128 + arow) * DIN + acol;
    const float* Bp = Wg + (size_t)brow * U_ + ncol0 + bcol;

    ull acc[8][4];
    #pragma unroll
    for (int j = 0; j < 8; j++)
        #pragma unroll
        for (int p = 0; p < 4; p++) acc[j][p] = 0ull;

    for (int k0 = 0; k0 < DIN; k0 += 8) {
        float4 av = *(const float4*)(Ap + k0);
        float4 bv = *(const float4*)(Bp + (size_t)k0 * U_);
        As[acol + 0][arow] = av.x; As[acol + 1][arow] = av.y;
        As[acol + 2][arow] = av.z; As[acol + 3][arow] = av.w;
        *(float4*)&Bs[brow][bcol] = bv;
        __syncthreads();
        #pragma unroll
        for (int kk = 0; kk < 8; kk++) {
            ulonglong2 a01 = *(const ulonglong2*)&As[kk][m0];
            ulonglong2 a23 = *(const ulonglong2*)&As[kk][m0 + 4];
            ull ap[4] = {a01.x, a01.y, a23.x, a23.y};
            float4 b0 = *(const float4*)&Bs[kk][n0];
            float4 b1 = *(const float4*)&Bs[kk][n0 + 4];
            ull bd[8] = {dup2(b0.x), dup2(b0.y), dup2(b0.z), dup2(b0.w),
                         dup2(b1.x), dup2(b1.y), dup2(b1.z), dup2(b1.w)};
            #pragma unroll
            for (int j = 0; j < 8; j++)
                #pragma unroll
                for (int p = 0; p < 4; p++) fma2(acc[j][p], bd[j], ap[p]);
        }
        __syncthreads();
    }

    const int gn0 = bn * 128 + n0;
    #pragma unroll
    for (int m = 0; m < 8; m++) {
        int gm = bm * 128 + m0 + m;
        int b = gm >> 7, t = gm & 127;            // X row m = b*T + t
        float* dst = pre + (size_t)(t * B_ + b) * NPRE + gn0;
        float v[8];
        #pragma unroll
        for (int j = 0; j < 8; j++) { float2 f = unpk(acc[j][m >> 1]); v[j] = (m & 1) ? f.y : f.x; }
        *(float4*)(dst)     = make_float4(v[0], v[1], v[2], v[3]);
        *(float4*)(dst + 4) = make_float4(v[4], v[5], v[6], v[7]);
    }
}

// ============================================================================
// Phase 2: the recurrence. 64 blocks x 8 batch rows, 256 threads, T=128 steps.
// h resident in SMEM ([k][m] transposed for packed f32x2 row-pairs).
// Per step: acc_zr[8,1024] = h @ [Wzh|Wrh]; z,r; rh = r*h; acc_h[8,512] = rh @ Whh;
// h_new = h + z*(tanh(pre_h + acc_h + bh) - h); store to g_h.
// ============================================================================
__global__ void __launch_bounds__(256, 1) k_rec(
    const float* __restrict__ pre,
    const float* __restrict__ Wzh, const float* __restrict__ Wrh, const float* __restrict__ Whh,
    const float* __restrict__ bz, const float* __restrict__ br, const float* __restrict__ bh,
    float* __restrict__ hall)
{
    __shared__ __align__(16) float hs [512][8];  // h   [k][m]
    __shared__ __align__(16) float rhs[512][8];  // r*h [k][m]
    __shared__ __align__(16) float zs [8][512];  // z   [m][n]

    const int tid  = threadIdx.x;
    const int lane = tid & 31;
    const int b0   = blockIdx.x * 8;

    for (int i = tid; i < 512 * 8; i += 256) (&hs[0][0])[i] = 0.0f;
    __syncthreads();

    // zr-GEMM column mapping: 4 consecutive cols of the 1024-wide [z|r] output
    const int  n0  = tid * 4;
    const bool isz = (n0 < 512);
    const int  c0  = isz ? n0 : (n0 - 512);
    const float* Wg = isz ? Wzh : Wrh;
    const float* bg = isz ? bz  : br;
    const float4 bias4 = *(const float4*)(bg + c0);

    // h-GEMM column mapping: 2 consecutive cols of the 512-wide output
    const int ch = tid * 2;
    const float2 biash = *(const float2*)(bh + ch);

    const int l8 = lane & 7, l4 = (lane >> 3) & 3;   // bank-conflict rotation for rhs stores

    for (int t = 0; t < T_; t++) {
        const float* pre_t = pre + (size_t)(t * B_ + b0) * NPRE;

        // Prefetch input-projection values for the zr elementwise (hides HBM latency)
        float4 pz[8];
        #pragma unroll
        for (int m = 0; m < 8; m++)
            pz[m] = *(const float4*)(pre_t + (size_t)m * NPRE + n0);

        // ----- zr GEMM: acc[col j][rowpair p] -----
        ull acc[4][4];
        #pragma unroll
        for (int j = 0; j < 4; j++)
            #pragma unroll
            for (int p = 0; p < 4; p++) acc[j][p] = 0ull;

        #pragma unroll 4
        for (int k = 0; k < U_; k++) {
            float4 w = *(const float4*)(Wg + (size_t)k * U_ + c0);
            ulonglong2 h01 = *(const ulonglong2*)&hs[k][0];
            ulonglong2 h23 = *(const ulonglong2*)&hs[k][4];
            ull w0 = dup2(w.x), w1 = dup2(w.y), w2 = dup2(w.z), w3 = dup2(w.w);
            fma2(acc[0][0], w0, h01.x); fma2(acc[0][1], w0, h01.y);
            fma2(acc[0][2], w0, h23.x); fma2(acc[0][3], w0, h23.y);
            fma2(acc[1][0], w1, h01.x); fma2(acc[1][1], w1, h01.y);
            fma2(acc[1][2], w1, h23.x); fma2(acc[1][3], w1, h23.y);
            fma2(acc[2][0], w2, h01.x); fma2(acc[2][1], w2, h01.y);
            fma2(acc[2][2], w2, h23.x); fma2(acc[2][3], w2, h23.y);
            fma2(acc[3][0], w3, h01.x); fma2(acc[3][1], w3, h01.y);
            fma2(acc[3][2], w3, h23.x); fma2(acc[3][3], w3, h23.y);
        }

        // ----- z / r elementwise -----
        float v[4][8];
        #pragma unroll
        for (int p = 0; p < 4; p++) {
            #pragma unroll
            for (int j = 0; j < 4; j++) {
                float2 f = unpk(acc[j][p]);
                float bj = f4c(bias4, j);
                v[j][2 * p]     = sigf(f.x + f4c(pz[2 * p],     j) + bj);
                v[j][2 * p + 1] = sigf(f.y + f4c(pz[2 * p + 1], j) + bj);
            }
        }
        if (isz) {
            #pragma unroll
            for (int m = 0; m < 8; m++)
                *(float4*)&zs[m][c0] = make_float4(v[0][m], v[1][m], v[2][m], v[3][m]);
        } else {
            // rhs[k][m] = r * h ; rotated (j,m) order -> conflict-free STS
            #pragma unroll
            for (int jj = 0; jj < 4; jj++) {
                int j = (jj + l4) & 3;
                #pragma unroll
                for (int mm = 0; mm < 8; mm++) {
                    int m = (mm + l8) & 7;
                    rhs[c0 + j][m] = v[j][m] * hs[c0 + j][m];
                }
            }
        }
        __syncthreads();   // rhs, zs complete

        // Prefetch pre_h
        float2 phh[8];
        #pragma unroll
        for (int m = 0; m < 8; m++)
            phh[m] = *(const float2*)(pre_t + (size_t)m * NPRE + 1024 + ch);

        // ----- h GEMM -----
        ull acch[2][4];
        #pragma unroll
        for (int j = 0; j < 2; j++)
            #pragma unroll
            for (int p = 0; p < 4; p++) acch[j][p] = 0ull;

        #pragma unroll 4
        for (int k = 0; k < U_; k++) {
            float2 w = *(const float2*)(Whh + (size_t)k * U_ + ch);
            ulonglong2 r01 = *(const ulonglong2*)&rhs[k][0];
            ulonglong2 r23 = *(const ulonglong2*)&rhs[k][4];
            ull w0 = dup2(w.x), w1 = dup2(w.y);
            fma2(acch[0][0], w0, r01.x); fma2(acch[0][1], w0, r01.y);
            fma2(acch[0][2], w0, r23.x); fma2(acch[0][3], w0, r23.y);
            fma2(acch[1][0], w1, r01.x); fma2(acch[1][1], w1, r01.y);
            fma2(acch[1][2], w1, r23.x); fma2(acch[1][3], w1, r23.y);
        }

        // ----- h elementwise + writeback -----
        float* hall_t = hall + (size_t)(t * B_ + b0) * U_ + ch;
        #pragma unroll
        for (int p = 0; p < 4; p++) {
            float hn[2][2];
            #pragma unroll
            for (int j = 0; j < 2; j++) {
                float2 f = unpk(acch[j][p]);
                float bj = j ? biash.y : biash.x;
                float pj0 = j ? phh[2 * p].y     : phh[2 * p].x;
                float pj1 = j ? phh[2 * p + 1].y : phh[2 * p + 1].x;
                float hc0 = tanhf(f.x + pj0 + bj);
                float hc1 = tanhf(f.y + pj1 + bj);
                float ho0 = hs[ch + j][2 * p];
                float ho1 = hs[ch + j][2 * p + 1];
                float z0 = zs[2 * p][ch + j];
                float z1 = zs[2 * p + 1][ch + j];
                hn[j][0] = ho0 + z0 * (hc0 - ho0);
                hn[j][1] = ho1 + z1 * (hc1 - ho1);
            }
            // update SMEM h (pairs along m are contiguous) + global h
            *(float2*)&hs[ch + 0][2 * p] = make_float2(hn[0][0], hn[0][1]);
            *(float2*)&hs[ch + 1][2 * p] = make_float2(hn[1][0], hn[1][1]);
            *(float2*)(hall_t + (size_t)(2 * p)     * U_) = make_float2(hn[0][0], hn[1][0]);
            *(float2*)(hall_t + (size_t)(2 * p + 1) * U_) = make_float2(hn[0][1], hn[1][1]);
        }
        __syncthreads();   // hs updated for next step
    }
}

// ============================================================================
// Phase 3: out[b][t][:] = g_h[t][b][:] @ W_o + b_o
// M=65536 (m' = t*512 + b), N=512, K=512. Same tiling as phase 1.
// ============================================================================
__global__ void __launch_bounds__(256) k_out(
    const float* __restrict__ H, const float* __restrict__ Wo, const float* __restrict__ bo,
    float* __restrict__ out)
{
    __shared__ __align__(16) float As[8][128];
    __shared__ __align__(16) float Bs[8][128];

    const int tid = threadIdx.x;
    const int bm = blockIdx.x, bn = blockIdx.y;

    const int tx = tid & 15, ty = tid >> 4;
    const int m0 = ty * 8, n0 = tx * 8;

    const int arow = tid >> 1, acol = (tid & 1) * 4;
    const int brow = tid >> 5, bcol = (tid & 31) * 4;
    const float* Ap = H  + (size_t)(bm * 128 + arow) * U_ + acol;
    const float* Bp = Wo + (size_t)brow * U_ + bn * 128 + bcol;

    ull acc[8][4];
    #pragma unroll
    for (int j = 0; j < 8; j++)
        #pragma unroll
        for (int p = 0; p < 4; p++) acc[j][p] = 0ull;

    for (int k0 = 0; k0 < U_; k0 += 8) {
        float4 av = *(const float4*)(Ap + k0);
        float4 bv = *(const float4*)(Bp + (size_t)k0 * U_);
        As[acol + 0][arow] = av.x; As[acol + 1][arow] = av.y;
        As[acol + 2][arow] = av.z; As[acol + 3][arow] = av.w;
        *(float4*)&Bs[brow][bcol] = bv;
        __syncthreads();
        #pragma unroll
        for (int kk = 0; kk < 8; kk++) {
            ulonglong2 a01 = *(const ulonglong2*)&As[kk][m0];
            ulonglong2 a23 = *(const ulonglong2*)&As[kk][m0 + 4];
            ull ap[4] = {a01.x, a01.y, a23.x, a23.y};
            float4 b0 = *(const float4*)&Bs[kk][n0];
            float4 b1 = *(const float4*)&Bs[kk][n0 + 4];
            ull bd[8] = {dup2(b0.x), dup2(b0.y), dup2(b0.z), dup2(b0.w),
                         dup2(b1.x), dup2(b1.y), dup2(b1.z), dup2(b1.w)};
            #pragma unroll
            for (int j = 0; j < 8; j++)
                #pragma unroll
                for (int p = 0; p < 4; p++) fma2(acc[j][p], bd[j], ap[p]);
        }
        __syncthreads();
    }

    const int gn0 = bn * 128 + n0;
    const float4 bo0 = *(const float4*)(bo + gn0);
    const float4 bo1 = *(const float4*)(bo + gn0 + 4);
    #pragma unroll
    for (int m = 0; m < 8; m++) {
        int mm = bm * 128 + m0 + m;            // h_all row = t*512 + b
        int b = mm & 511, t = mm >> 9;
        float* dst = out + (size_t)(b * T_ + t) * U_ + gn0;
        float v[8];
        #pragma unroll
        for (int j = 0; j < 8; j++) { float2 f = unpk(acc[j][m >> 1]); v[j] = (m & 1) ? f.y : f.x; }
        *(float4*)(dst)     = make_float4(v[0] + bo0.x, v[1] + bo0.y, v[2] + bo0.z, v[3] + bo0.w);
        *(float4*)(dst + 4) = make_float4(v[4] + bo1.x, v[5] + bo1.y, v[6] + bo1.z, v[7] + bo1.w);
    }
}

// ============================================================================
extern "C" void kernel_launch(void* const* d_in, const int* in_sizes, int n_in,
                              void* d_out, int out_size)
{
    const float* x    = (const float*)d_in[0];
    const float* Wzx  = (const float*)d_in[1];
    const float* Wrx  = (const float*)d_in[2];
    const float* Whx  = (const float*)d_in[3];
    const float* Wzh  = (const float*)d_in[4];
    const float* Wrh  = (const float*)d_in[5];
    const float* Whh  = (const float*)d_in[6];
    const float* bz   = (const float*)d_in[7];
    const float* br   = (const float*)d_in[8];
    const float* bh   = (const float*)d_in[9];
    // d_in[10..12] = W_q, W_k, W_v : dead code in the reference (attn unused)
    const float* Wo   = (const float*)d_in[13];
    const float* bo   = (const float*)d_in[14];
    float* out = (float*)d_out;

    float* pre;  cudaGetSymbolAddress((void**)&pre,  g_pre);
    float* hall; cudaGetSymbolAddress((void**)&hall, g_h);

    k_pre<<<dim3(512, 12), 256>>>(x, Wzx, Wrx, Whx, pre);
    k_rec<<<64, 256>>>(pre, Wzh, Wrh, Whh, bz, br, bh, hall);
    k_out<<<dim3(512, 4), 256>>>(hall, Wo, bo, out);
    (void)in_sizes; (void)n_in; (void)out_size;
}

// round 5
// speedup vs baseline: 1.7238x; 1.7238x over previous
#include <cuda_runtime.h>
#include <math.h>
#include <stdint.h>

#define B_   512
#define T_   128
#define DIN  256
#define U_   512
#define NPRE 1536   // [z | r | h] precomputed input projections

// Scratch (static device arrays — allocation-free rule)
__device__ float g_pre[(size_t)T_ * B_ * NPRE];  // [t][b][1536]
__device__ float g_h  [(size_t)T_ * B_ * U_];    // [t][b][512]

typedef unsigned long long ull;

__device__ __forceinline__ ull dup2(float v) {
    ull r; asm("mov.b64 %0, {%1, %1};" : "=l"(r) : "f"(v)); return r;
}
__device__ __forceinline__ ull pack2(float lo, float hi) {
    ull r; asm("mov.b64 %0, {%1, %2};" : "=l"(r) : "f"(lo), "f"(hi)); return r;
}
__device__ __forceinline__ void fma2(ull& d, ull a, ull b) {
    asm("fma.rn.f32x2 %0, %1, %2, %0;" : "+l"(d) : "l"(a), "l"(b));
}
__device__ __forceinline__ ull mul2(ull a, ull b) {
    ull r; asm("mul.rn.f32x2 %0, %1, %2;" : "=l"(r) : "l"(a), "l"(b)); return r;
}
__device__ __forceinline__ float2 unpk(ull v) {
    float2 f; asm("mov.b64 {%0, %1}, %2;" : "=f"(f.x), "=f"(f.y) : "l"(v)); return f;
}
__device__ __forceinline__ float sigf(float x) {
    return 1.0f / (1.0f + expf(-x));
}
__device__ __forceinline__ uint32_t smem_u32(const void* p) {
    uint32_t a;
    asm("{ .reg .u64 t; cvta.to.shared.u64 t, %1; cvt.u32.u64 %0, t; }" : "=r"(a) : "l"(p));
    return a;
}
__device__ __forceinline__ void st_rem2(uint32_t laddr, uint32_t rank, ull a, ull b) {
    uint32_t ra;
    asm volatile("mapa.shared::cluster.u32 %0, %1, %2;" : "=r"(ra) : "r"(laddr), "r"(rank));
    asm volatile("st.shared::cluster.v2.b64 [%0], {%1, %2};" :: "r"(ra), "l"(a), "l"(b) : "memory");
}
__device__ __forceinline__ void cluster_sync() {
    asm volatile("barrier.cluster.arrive.aligned;" ::: "memory");
    asm volatile("barrier.cluster.wait.aligned;" ::: "memory");
}

// ============================================================================
// Phase 1: pre[t][b][0:1536] = x[b][t][:] @ [Wzx | Wrx | Whx]
// M=65536 (m = b*128 + t), N=1536, K=256. 128x128 tiles, BK=8, 8x8/thread,
// f32x2, double-buffered global loads.
// ============================================================================
__global__ void __launch_bounds__(256) k_pre(
    const float* __restrict__ X,
    const float* __restrict__ Wzx, const float* __restrict__ Wrx, const float* __restrict__ Whx,
    float* __restrict__ pre)
{
    __shared__ __align__(16) float As[8][128];   // [k][m] transposed
    __shared__ __align__(16) float Bs[8][128];   // [k][n]

    const int tid = threadIdx.x;
    const int bm = blockIdx.x, bn = blockIdx.y;
    const int gate = (bn * 128) >> 9;                 // each 128-wide tile is within one gate
    const float* Wg = gate == 0 ? Wzx : (gate == 1 ? Wrx : Whx);
    const int ncol0 = bn * 128 - gate * 512;

    const int tx = tid & 15, ty = tid >> 4;
    const int m0 = ty * 8, n0 = tx * 8;

    const int arow = tid >> 1, acol = (tid & 1) * 4;
    const int brow = tid >> 5, bcol = (tid & 31) * 4;
    const float* Ap = X  + (size_t)(bm * 128 + arow) * DIN + acol;
    const float* Bp = Wg + (size_t)brow * U_ + ncol0 + bcol;

    ull acc[8][4];
    #pragma unroll
    for (int j = 0; j < 8; j++)
        #pragma unroll
        for (int p = 0; p < 4; p++) acc[j][p] = 0ull;

    float4 av = *(const float4*)(Ap);
    float4 bv = *(const float4*)(Bp);

    for (int k0 = 0; k0 < DIN; k0 += 8) {
        As[acol + 0][arow] = av.x; As[acol + 1][arow] = av.y;
        As[acol + 2][arow] = av.z; As[acol + 3][arow] = av.w;
        *(float4*)&Bs[brow][bcol] = bv;
        __syncthreads();
        if (k0 + 8 < DIN) {
            av = *(const float4*)(Ap + k0 + 8);
            bv = *(const float4*)(Bp + (size_t)(k0 + 8) * U_);
        }
        #pragma unroll
        for (int kk = 0; kk < 8; kk++) {
            ulonglong2 a01 = *(const ulonglong2*)&As[kk][m0];
            ulonglong2 a23 = *(const ulonglong2*)&As[kk][m0 + 4];
            ull ap[4] = {a01.x, a01.y, a23.x, a23.y};
            float4 b0 = *(const float4*)&Bs[kk][n0];
            float4 b1 = *(const float4*)&Bs[kk][n0 + 4];
            ull bd[8] = {dup2(b0.x), dup2(b0.y), dup2(b0.z), dup2(b0.w),
                         dup2(b1.x), dup2(b1.y), dup2(b1.z), dup2(b1.w)};
            #pragma unroll
            for (int j = 0; j < 8; j++)
                #pragma unroll
                for (int p = 0; p < 4; p++) fma2(acc[j][p], bd[j], ap[p]);
        }
        __syncthreads();
    }

    const int gn0 = bn * 128 + n0;
    #pragma unroll
    for (int m = 0; m < 8; m++) {
        int gm = bm * 128 + m0 + m;
        int b = gm >> 7, t = gm & 127;            // X row m = b*T + t
        float* dst = pre + (size_t)(t * B_ + b) * NPRE + gn0;
        float v[8];
        #pragma unroll
        for (int j = 0; j < 8; j++) { float2 f = unpk(acc[j][m >> 1]); v[j] = (m & 1) ? f.y : f.x; }
        *(float4*)(dst)     = make_float4(v[0], v[1], v[2], v[3]);
        *(float4*)(dst + 4) = make_float4(v[4], v[5], v[6], v[7]);
    }
}

// ============================================================================
// Phase 2: the recurrence, cluster version.
// 32 clusters x 4 CTAs (128 CTAs, 1/SM). Cluster owns 16 batch rows; CTA rank j
// owns columns [j*128,(j+1)*128) of z, r and h. Full h and r*h replicated per
// CTA in dynamic SMEM; slices broadcast to peers via DSMEM each phase.
// Weights ping-pong prefetched 8 deep from L2 into registers.
// ============================================================================
#define ZR_STEP(BUF, KB)                                                        \
    do {                                                                        \
        _Pragma("unroll")                                                       \
        for (int i_ = 0; i_ < 8; i_++) {                                        \
            const float* hp_ = hs + (size_t)((KB) + i_) * 16 + rh8;             \
            ulonglong2 h01_ = *(const ulonglong2*)hp_;                          \
            ulonglong2 h23_ = *(const ulonglong2*)(hp_ + 4);                    \
            ull w0_ = dup2(BUF[i_].x), w1_ = dup2(BUF[i_].y);                   \
            fma2(acc[0][0], w0_, h01_.x); fma2(acc[0][1], w0_, h01_.y);         \
            fma2(acc[0][2], w0_, h23_.x); fma2(acc[0][3], w0_, h23_.y);         \
            fma2(acc[1][0], w1_, h01_.x); fma2(acc[1][1], w1_, h01_.y);         \
            fma2(acc[1][2], w1_, h23_.x); fma2(acc[1][3], w1_, h23_.y);         \
        }                                                                       \
    } while (0)

#define H_STEP(BUF, KB)                                                         \
    do {                                                                        \
        _Pragma("unroll")                                                       \
        for (int i_ = 0; i_ < 8; i_++) {                                        \
            const float* rp_ = rhs + (size_t)((KB) + i_) * 16 + rh8;            \
            ulonglong2 r01_ = *(const ulonglong2*)rp_;                          \
            ulonglong2 r23_ = *(const ulonglong2*)(rp_ + 4);                    \
            ull w_ = dup2(BUF[i_]);                                             \
            fma2(acch[0], w_, r01_.x); fma2(acch[1], w_, r01_.y);               \
            fma2(acch[2], w_, r23_.x); fma2(acch[3], w_, r23_.y);               \
        }                                                                       \
    } while (0)

__global__ void __launch_bounds__(256) __cluster_dims__(4, 1, 1) k_rec(
    const float* __restrict__ pre,
    const float* __restrict__ Wzh, const float* __restrict__ Wrh, const float* __restrict__ Whh,
    const float* __restrict__ bz, const float* __restrict__ br, const float* __restrict__ bh,
    float* __restrict__ hall)
{
    extern __shared__ __align__(16) float smf[];
    float* hs  = smf;           // [512][16]  h,   [k][m]
    float* rhs = smf + 8192;    // [512][16]  r*h, [k][m]
    float* zsm = smf + 16384;   // [16][128]  z,   [m][c_local]

    const int tid   = threadIdx.x;
    const int rank  = blockIdx.x & 3;
    const int cid   = blockIdx.x >> 2;
    const int b0    = cid * 16;
    const int jbase = rank * 128;

    const uint32_t sb      = smem_u32(smf);
    const uint32_t RHS_OFF = 32768;

    // zr-phase mapping: rowhalf (8 rows) x 2 cols; zsel picks z vs r
    const int rh8  = (tid >> 7) * 8;
    const int cp   = tid & 63;
    const int zsel = (tid >> 6) & 1;
    const int colw = jbase + 2 * cp;
    const float* Wzr = zsel ? Wrh : Wzh;
    const float2 bias2 = *(const float2*)((zsel ? br : bz) + colw);
    const int precolzr = (zsel ? 512 : 0) + colw;

    // h-phase mapping: rowhalf x 1 col
    const int ch  = tid & 127;
    const int k0h = jbase + ch;
    const float bhc = bh[k0h];

    for (int i = tid; i < 8192; i += 256) hs[i] = 0.0f;
    cluster_sync();

    for (int t = 0; t < T_; t++) {
        const float* pre_t = pre + (size_t)(t * B_ + b0) * NPRE;

        // prefetch input-projection values for zr elementwise
        float2 pz[8];
        #pragma unroll
        for (int mi = 0; mi < 8; mi++)
            pz[mi] = *(const float2*)(pre_t + (size_t)(rh8 + mi) * NPRE + precolzr);

        // ---------------- zr GEMM: 2 cols x 8 rows, K=512 ----------------
        ull acc[2][4];
        #pragma unroll
        for (int j = 0; j < 2; j++)
            #pragma unroll
            for (int p = 0; p < 4; p++) acc[j][p] = 0ull;

        {
            const float* wp = Wzr + colw;
            float2 wa[8], wb[8];
            #pragma unroll
            for (int i = 0; i < 8; i++) wa[i] = *(const float2*)(wp + (size_t)i * U_);
            for (int kb = 0; kb < 512; kb += 16) {
                #pragma unroll
                for (int i = 0; i < 8; i++) wb[i] = *(const float2*)(wp + (size_t)(kb + 8 + i) * U_);
                ZR_STEP(wa, kb);
                if (kb + 16 < 512) {
                    #pragma unroll
                    for (int i = 0; i < 8; i++) wa[i] = *(const float2*)(wp + (size_t)(kb + 16 + i) * U_);
                }
                ZR_STEP(wb, kb + 8);
            }
        }

        // ---------------- z / r elementwise ----------------
        float v0[8], v1[8];
        #pragma unroll
        for (int p = 0; p < 4; p++) {
            float2 f0 = unpk(acc[0][p]), f1 = unpk(acc[1][p]);
            v0[2 * p]     = sigf(f0.x + pz[2 * p].x     + bias2.x);
            v0[2 * p + 1] = sigf(f0.y + pz[2 * p + 1].x + bias2.x);
            v1[2 * p]     = sigf(f1.x + pz[2 * p].y     + bias2.y);
            v1[2 * p + 1] = sigf(f1.y + pz[2 * p + 1].y + bias2.y);
        }
        if (!zsel) {
            // z -> local zsm (z cols == own h cols, no exchange needed)
            #pragma unroll
            for (int mi = 0; mi < 8; mi++)
                *(float2*)(zsm + (size_t)(rh8 + mi) * 128 + 2 * cp) = make_float2(v0[mi], v1[mi]);
        } else {
            // r -> rhs[k][m] = r * h, local + 3 peers
            #pragma unroll
            for (int j = 0; j < 2; j++) {
                const int k0 = colw + j;
                float* hp = hs + (size_t)k0 * 16 + rh8;
                ulonglong2 h01 = *(const ulonglong2*)hp;
                ulonglong2 h23 = *(const ulonglong2*)(hp + 4);
                const float* vv = j ? v1 : v0;
                ull r0 = mul2(pack2(vv[0], vv[1]), h01.x);
                ull r1 = mul2(pack2(vv[2], vv[3]), h01.y);
                ull r2 = mul2(pack2(vv[4], vv[5]), h23.x);
                ull r3 = mul2(pack2(vv[6], vv[7]), h23.y);
                float* rp = rhs + (size_t)k0 * 16 + rh8;
                *(ulonglong2*)rp       = make_ulonglong2(r0, r1);
                *(ulonglong2*)(rp + 4) = make_ulonglong2(r2, r3);
                const uint32_t la = sb + RHS_OFF + (uint32_t)(k0 * 16 + rh8) * 4;
                #pragma unroll
                for (int d = 1; d < 4; d++) {
                    const uint32_t pr = (rank + d) & 3;
                    st_rem2(la,      pr, r0, r1);
                    st_rem2(la + 16, pr, r2, r3);
                }
            }
        }

        cluster_sync();   // rhs complete everywhere; zsm complete locally

        // prefetch pre_h
        float phh[8];
        #pragma unroll
        for (int mi = 0; mi < 8; mi++)
            phh[mi] = pre_t[(size_t)(rh8 + mi) * NPRE + 1024 + k0h];

        // ---------------- h GEMM: 1 col x 8 rows, K=512 ----------------
        ull acch[4];
        #pragma unroll
        for (int p = 0; p < 4; p++) acch[p] = 0ull;

        {
            const float* wp = Whh + k0h;
            float wa[8], wb[8];
            #pragma unroll
            for (int i = 0; i < 8; i++) wa[i] = wp[(size_t)i * U_];
            for (int kb = 0; kb < 512; kb += 16) {
                #pragma unroll
                for (int i = 0; i < 8; i++) wb[i] = wp[(size_t)(kb + 8 + i) * U_];
                H_STEP(wa, kb);
                if (kb + 16 < 512) {
                    #pragma unroll
                    for (int i = 0; i < 8; i++) wa[i] = wp[(size_t)(kb + 16 + i) * U_];
                }
                H_STEP(wb, kb + 8);
            }
        }

        // ---------------- h elementwise + writeback ----------------
        float hc[8];
        #pragma unroll
        for (int p = 0; p < 4; p++) {
            float2 f = unpk(acch[p]);
            hc[2 * p]     = tanhf(f.x + phh[2 * p]     + bhc);
            hc[2 * p + 1] = tanhf(f.y + phh[2 * p + 1] + bhc);
        }
        float* hp = hs + (size_t)k0h * 16 + rh8;
        ulonglong2 o01 = *(const ulonglong2*)hp;
        ulonglong2 o23 = *(const ulonglong2*)(hp + 4);
        float ho[8];
        { float2 f;
          f = unpk(o01.x); ho[0] = f.x; ho[1] = f.y;
          f = unpk(o01.y); ho[2] = f.x; ho[3] = f.y;
          f = unpk(o23.x); ho[4] = f.x; ho[5] = f.y;
          f = unpk(o23.y); ho[6] = f.x; ho[7] = f.y; }
        float hn[8];
        #pragma unroll
        for (int mi = 0; mi < 8; mi++) {
            float z = zsm[(size_t)(rh8 + mi) * 128 + ch];
            hn[mi] = ho[mi] + z * (hc[mi] - ho[mi]);
        }
        ull n0 = pack2(hn[0], hn[1]), n1 = pack2(hn[2], hn[3]);
        ull n2 = pack2(hn[4], hn[5]), n3 = pack2(hn[6], hn[7]);
        *(ulonglong2*)hp       = make_ulonglong2(n0, n1);
        *(ulonglong2*)(hp + 4) = make_ulonglong2(n2, n3);
        const uint32_t la = sb + (uint32_t)(k0h * 16 + rh8) * 4;
        #pragma unroll
        for (int d = 1; d < 4; d++) {
            const uint32_t pr = (rank + d) & 3;
            st_rem2(la,      pr, n0, n1);
            st_rem2(la + 16, pr, n2, n3);
        }
        float* gh = hall + (size_t)(t * B_ + b0 + rh8) * U_ + k0h;
        #pragma unroll
        for (int mi = 0; mi < 8; mi++)
            gh[(size_t)mi * U_] = hn[mi];

        cluster_sync();   // hs updated everywhere for next step
    }
}

// ============================================================================
// Phase 3: out[b][t][:] = g_h[t][b][:] @ W_o + b_o
// M=65536 (m' = t*512 + b), N=512, K=512. Double-buffered.
// ============================================================================
__global__ void __launch_bounds__(256) k_out(
    const float* __restrict__ H, const float* __restrict__ Wo, const float* __restrict__ bo,
    float* __restrict__ out)
{
    __shared__ __align__(16) float As[8][128];
    __shared__ __align__(16) float Bs[8][128];

    const int tid = threadIdx.x;
    const int bm = blockIdx.x, bn = blockIdx.y;

    const int tx = tid & 15, ty = tid >> 4;
    const int m0 = ty * 8, n0 = tx * 8;

    const int arow = tid >> 1, acol = (tid & 1) * 4;
    const int brow = tid >> 5, bcol = (tid & 31) * 4;
    const float* Ap = H  + (size_t)(bm * 128 + arow) * U_ + acol;
    const float* Bp = Wo + (size_t)brow * U_ + bn * 128 + bcol;

    ull acc[8][4];
    #pragma unroll
    for (int j = 0; j < 8; j++)
        #pragma unroll
        for (int p = 0; p < 4; p++) acc[j][p] = 0ull;

    float4 av = *(const float4*)(Ap);
    float4 bv = *(const float4*)(Bp);

    for (int k0 = 0; k0 < U_; k0 += 8) {
        As[acol + 0][arow] = av.x; As[acol + 1][arow] = av.y;
        As[acol + 2][arow] = av.z; As[acol + 3][arow] = av.w;
        *(float4*)&Bs[brow][bcol] = bv;
        __syncthreads();
        if (k0 + 8 < U_) {
            av = *(const float4*)(Ap + k0 + 8);
            bv = *(const float4*)(Bp + (size_t)(k0 + 8) * U_);
        }
        #pragma unroll
        for (int kk = 0; kk < 8; kk++) {
            ulonglong2 a01 = *(const ulonglong2*)&As[kk][m0];
            ulonglong2 a23 = *(const ulonglong2*)&As[kk][m0 + 4];
            ull ap[4] = {a01.x, a01.y, a23.x, a23.y};
            float4 b0 = *(const float4*)&Bs[kk][n0];
            float4 b1 = *(const float4*)&Bs[kk][n0 + 4];
            ull bd[8] = {dup2(b0.x), dup2(b0.y), dup2(b0.z), dup2(b0.w),
                         dup2(b1.x), dup2(b1.y), dup2(b1.z), dup2(b1.w)};
            #pragma unroll
            for (int j = 0; j < 8; j++)
                #pragma unroll
                for (int p = 0; p < 4; p++) fma2(acc[j][p], bd[j], ap[p]);
        }
        __syncthreads();
    }

    const int gn0 = bn * 128 + n0;
    const float4 bo0 = *(const float4*)(bo + gn0);
    const float4 bo1 = *(const float4*)(bo + gn0 + 4);
    #pragma unroll
    for (int m = 0; m < 8; m++) {
        int mm = bm * 128 + m0 + m;            // h_all row = t*512 + b
        int b = mm & 511, t = mm >> 9;
        float* dst = out + (size_t)(b * T_ + t) * U_ + gn0;
        float v[8];
        #pragma unroll
        for (int j = 0; j < 8; j++) { float2 f = unpk(acc[j][m >> 1]); v[j] = (m & 1) ? f.y : f.x; }
        *(float4*)(dst)     = make_float4(v[0] + bo0.x, v[1] + bo0.y, v[2] + bo0.z, v[3] + bo0.w);
        *(float4*)(dst + 4) = make_float4(v[4] + bo1.x, v[5] + bo1.y, v[6] + bo1.z, v[7] + bo1.w);
    }
}

// ============================================================================
extern "C" void kernel_launch(void* const* d_in, const int* in_sizes, int n_in,
                              void* d_out, int out_size)
{
    const float* x    = (const float*)d_in[0];
    const float* Wzx  = (const float*)d_in[1];
    const float* Wrx  = (const float*)d_in[2];
    const float* Whx  = (const float*)d_in[3];
    const float* Wzh  = (const float*)d_in[4];
    const float* Wrh  = (const float*)d_in[5];
    const float* Whh  = (const float*)d_in[6];
    const float* bz   = (const float*)d_in[7];
    const float* br   = (const float*)d_in[8];
    const float* bh   = (const float*)d_in[9];
    // d_in[10..12] = W_q, W_k, W_v : dead code in the reference (attn unused)
    const float* Wo   = (const float*)d_in[13];
    const float* bo   = (const float*)d_in[14];
    float* out = (float*)d_out;

    float* pre;  cudaGetSymbolAddress((void**)&pre,  g_pre);
    float* hall; cudaGetSymbolAddress((void**)&hall, g_h);

    const int REC_SMEM = 73728;  // hs 32K + rhs 32K + zsm 8K
    cudaFuncSetAttribute(k_rec, cudaFuncAttributeMaxDynamicSharedMemorySize, REC_SMEM);

    k_pre<<<dim3(512, 12), 256>>>(x, Wzx, Wrx, Whx, pre);
    k_rec<<<128, 256, REC_SMEM>>>(pre, Wzh, Wrh, Whh, bz, br, bh, hall);
    k_out<<<dim3(512, 4), 256>>>(hall, Wo, bo, out);
    (void)in_sizes; (void)n_in; (void)out_size;
}